// round 2
// baseline (speedup 1.0000x reference)
#include <cuda_runtime.h>

#define BATCH   4096
#define FEAT    40960
#define ACCUM   512
#define H1      32
#define H2      32
#define MAXIDX  128

// Scratch (device globals — no allocations allowed)
__device__ float g_ftT[(size_t)FEAT * ACCUM];          // transposed ft weights [FEAT][ACCUM]
__device__ int   g_idxw[(size_t)BATCH * MAXIDX];
__device__ int   g_idxb[(size_t)BATCH * MAXIDX];
__device__ int   g_cntw[BATCH];
__device__ int   g_cntb[BATCH];
__device__ int   g_stm_mode;   // 0 = byte bool, 1 = int32, 2 = float32

// ---------------------------------------------------------------------------
// K0: detect stm dtype (reads only first 4096 bytes — safe under all layouts)
//     + zero the per-row index counters (graph replays need fresh counters).
// ---------------------------------------------------------------------------
__global__ void k0_prep(const unsigned char* __restrict__ stm) {
    __shared__ int bad_int, bad_f32;
    if (threadIdx.x == 0) { bad_int = 0; bad_f32 = 0; }
    __syncthreads();
    for (int g = threadIdx.x; g < 1024; g += blockDim.x) {
        unsigned char b0 = stm[4*g+0], b1 = stm[4*g+1];
        unsigned char b2 = stm[4*g+2], b3 = stm[4*g+3];
        if (!((b1 | b2 | b3) == 0 && b0 <= 1)) atomicOr(&bad_int, 1);
        bool zero = (b0 | b1 | b2 | b3) == 0;
        bool one  = (b0 == 0 && b1 == 0 && b2 == 0x80 && b3 == 0x3F);
        if (!(zero || one)) atomicOr(&bad_f32, 1);
    }
    for (int i = threadIdx.x; i < BATCH; i += blockDim.x) {
        g_cntw[i] = 0;
        g_cntb[i] = 0;
    }
    __syncthreads();
    if (threadIdx.x == 0)
        g_stm_mode = (!bad_int) ? 1 : ((!bad_f32) ? 2 : 0);
}

// ---------------------------------------------------------------------------
// K1: fused transpose + sparsify. Block-type interleaved 5:2 so both HBM
// streams (168 MB transpose traffic, 1.34 GB feature stream) run concurrently.
// Feature reads use __ldcs (evict-first) so g_ftT lines stay L2-resident.
//   grid = 28672 blocks of 256 threads
//   bid%7 <  5 -> transpose tile   (20480 tiles: 1280 x 16 of 32x32)
//   bid%7 >= 5 -> row sparsify     (8192 rows: 4096 white + 4096 black)
// ---------------------------------------------------------------------------
__global__ __launch_bounds__(256) void k1_transpose_sparsify(
    const float* __restrict__ ftw,
    const float* __restrict__ wf,
    const float* __restrict__ bf)
{
    const int bid = blockIdx.x;
    const int sel = bid % 7;

    if (sel < 5) {
        // ------- transpose tile -------
        __shared__ float tile[32][33];
        int t_idx = (bid / 7) * 5 + sel;          // [0, 20480)
        int fx = (t_idx % 1280) * 32;             // feature origin
        int oy = (t_idx / 1280) * 32;             // accum-output origin
        int tx = threadIdx.x & 31, ty = threadIdx.x >> 5;   // (32, 8)
        #pragma unroll
        for (int j = 0; j < 32; j += 8)
            tile[ty + j][tx] = __ldcs(&ftw[(size_t)(oy + ty + j) * FEAT + (fx + tx)]);
        __syncthreads();
        #pragma unroll
        for (int j = 0; j < 32; j += 8)
            g_ftT[(size_t)(fx + ty + j) * ACCUM + (oy + tx)] = tile[tx][ty + j];
    } else {
        // ------- row sparsify -------
        int s_idx = (bid / 7) * 2 + (sel - 5);    // [0, 8192)
        const bool is_b = s_idx >= BATCH;
        const int  row  = is_b ? s_idx - BATCH : s_idx;
        const float4* src = (const float4*)((is_b ? bf : wf) + (size_t)row * FEAT);
        int*       idxout = (is_b ? g_idxb : g_idxw) + (size_t)row * MAXIDX;
        int*       cnt    = (is_b ? g_cntb : g_cntw) + row;

        const int t = threadIdx.x;
        #pragma unroll
        for (int i = 0; i < FEAT / 4 / 256; i++) {   // 40 iterations
            int vi = t + i * 256;
            float4 v = __ldcs(&src[vi]);
            if (v.x != 0.f) { int p = atomicAdd(cnt, 1); if (p < MAXIDX) idxout[p] = 4*vi + 0; }
            if (v.y != 0.f) { int p = atomicAdd(cnt, 1); if (p < MAXIDX) idxout[p] = 4*vi + 1; }
            if (v.z != 0.f) { int p = atomicAdd(cnt, 1); if (p < MAXIDX) idxout[p] = 4*vi + 2; }
            if (v.w != 0.f) { int p = atomicAdd(cnt, 1); if (p < MAXIDX) idxout[p] = 4*vi + 3; }
        }
    }
}

// ---------------------------------------------------------------------------
// K2: per-row gather + MLP head. One block per batch row, 512 threads
// (thread t = accumulator channel t). Gathers hit L2-resident g_ftT.
// ---------------------------------------------------------------------------
__global__ __launch_bounds__(512, 3) void k2_gather_mlp(
    const unsigned char* __restrict__ stm_raw,
    const float* __restrict__ ft_b,
    const float* __restrict__ l1_w, const float* __restrict__ l1_b,
    const float* __restrict__ l2_w, const float* __restrict__ l2_b,
    const float* __restrict__ out_w, const float* __restrict__ out_b,
    float* __restrict__ out)
{
    const int row = blockIdx.x;
    const int t   = threadIdx.x;

    __shared__ int   idxw[MAXIDX], idxb[MAXIDX];
    __shared__ float x[2 * ACCUM];
    __shared__ float v1[H1];

    const int cw = min(g_cntw[row], MAXIDX);
    const int cb = min(g_cntb[row], MAXIDX);

    if (t < MAXIDX) {
        idxw[t] = (t < cw) ? g_idxw[(size_t)row * MAXIDX + t] : 0;
    } else if (t < 2 * MAXIDX) {
        int u = t - MAXIDX;
        idxb[u] = (u < cb) ? g_idxb[(size_t)row * MAXIDX + u] : 0;
    }
    __syncthreads();

    // ---- accumulate (4-way MLP) ----
    float a0 = 0.f, a1 = 0.f, a2 = 0.f, a3 = 0.f;
    int k = 0;
    for (; k + 4 <= cw; k += 4) {
        a0 += g_ftT[(size_t)idxw[k+0] * ACCUM + t];
        a1 += g_ftT[(size_t)idxw[k+1] * ACCUM + t];
        a2 += g_ftT[(size_t)idxw[k+2] * ACCUM + t];
        a3 += g_ftT[(size_t)idxw[k+3] * ACCUM + t];
    }
    for (; k < cw; k++) a0 += g_ftT[(size_t)idxw[k] * ACCUM + t];
    float accw = ft_b[t] + (a0 + a1) + (a2 + a3);

    float b0 = 0.f, b1 = 0.f, b2 = 0.f, b3 = 0.f;
    k = 0;
    for (; k + 4 <= cb; k += 4) {
        b0 += g_ftT[(size_t)idxb[k+0] * ACCUM + t];
        b1 += g_ftT[(size_t)idxb[k+1] * ACCUM + t];
        b2 += g_ftT[(size_t)idxb[k+2] * ACCUM + t];
        b3 += g_ftT[(size_t)idxb[k+3] * ACCUM + t];
    }
    for (; k < cb; k++) b0 += g_ftT[(size_t)idxb[k] * ACCUM + t];
    float accb = ft_b[t] + (b0 + b1) + (b2 + b3);

    // screlu
    accw = fminf(fmaxf(accw, 0.f), 1.f); accw *= accw;
    accb = fminf(fmaxf(accb, 0.f), 1.f); accb *= accb;

    // stm select
    bool s;
    {
        int mode = g_stm_mode;
        if (mode == 1)      s = ((const int*)stm_raw)[row] != 0;
        else if (mode == 2) s = ((const float*)stm_raw)[row] != 0.f;
        else                s = stm_raw[row] != 0;
    }
    x[t]         = s ? accb : accw;
    x[ACCUM + t] = s ? accw : accb;
    __syncthreads();

    // ---- L1: 32 outputs x 1024-dot; 16 warps x 2 outputs ----
    const int warp = t >> 5, lane = t & 31;
    #pragma unroll
    for (int oo = 0; oo < 2; oo++) {
        int o = warp * 2 + oo;
        const float* w1 = l1_w + (size_t)o * (2 * ACCUM);
        float sum = 0.f;
        #pragma unroll
        for (int j = lane; j < 2 * ACCUM; j += 32)
            sum += x[j] * __ldg(&w1[j]);
        #pragma unroll
        for (int off = 16; off > 0; off >>= 1)
            sum += __shfl_down_sync(0xffffffffu, sum, off);
        if (lane == 0) {
            sum += l1_b[o];
            sum = fminf(fmaxf(sum, 0.f), 1.f);
            v1[o] = sum * sum;
        }
    }
    __syncthreads();

    // ---- L2 layer + output head (warp 0) ----
    if (warp == 0) {
        float sum = l2_b[lane];
        #pragma unroll
        for (int j = 0; j < H1; j++)
            sum += v1[j] * __ldg(&l2_w[lane * H1 + j]);
        sum = fminf(fmaxf(sum, 0.f), 1.f);
        float vv = sum * sum * __ldg(&out_w[lane]);
        #pragma unroll
        for (int off = 16; off > 0; off >>= 1)
            vv += __shfl_down_sync(0xffffffffu, vv, off);
        if (lane == 0) out[row] = vv + out_b[0];
    }
}

// ---------------------------------------------------------------------------
extern "C" void kernel_launch(void* const* d_in, const int* in_sizes, int n_in,
                              void* d_out, int out_size) {
    const float*         wf    = (const float*)d_in[0];
    const float*         bf    = (const float*)d_in[1];
    const unsigned char* stm   = (const unsigned char*)d_in[2];
    const float*         ft_w  = (const float*)d_in[3];
    const float*         ft_b  = (const float*)d_in[4];
    const float*         l1_w  = (const float*)d_in[5];
    const float*         l1_b  = (const float*)d_in[6];
    const float*         l2_w  = (const float*)d_in[7];
    const float*         l2_b  = (const float*)d_in[8];
    const float*         out_w = (const float*)d_in[9];
    const float*         out_b = (const float*)d_in[10];
    float*               out   = (float*)d_out;

    k0_prep<<<1, 256>>>(stm);
    k1_transpose_sparsify<<<28672, 256>>>(ft_w, wf, bf);
    k2_gather_mlp<<<BATCH, 512>>>(stm, ft_b, l1_w, l1_b,
                                  l2_w, l2_b, out_w, out_b, out);
}